// round 1
// baseline (speedup 1.0000x reference)
#include <cuda_runtime.h>
#include <cuda_bf16.h>
#include <math.h>

#define B_  2
#define S_  2048
#define D_  1024
#define H_  16
#define DK_ 64
#define SCALE_ 0.125f
#define NEG_ (-60000.0f)

// ---------------- scratch (device globals; no allocation allowed) ----------------
__device__ float g_qkv[B_ * S_ * 3 * D_];   // [B,S,3D]
__device__ float g_ctx[B_ * S_ * D_];       // [B,S,D]

// ---------------- SGEMM: C[M,N] = A[M,K] * B[N,K]^T (both row-major, K contiguous) ----------------
// 128x128 tile, BK=8, 256 threads, 8x8 per thread, strided register mapping.
#define BM 128
#define BN 128
#define BK 8
#define TM 8
#define TN 8

__global__ __launch_bounds__(256)
void sgemm_abt(const float* __restrict__ A, const float* __restrict__ Bm,
               float* __restrict__ C, int M, int N, int K)
{
    __shared__ float As[BK][BM];
    __shared__ float Bs[BK][BN];

    const int tid = threadIdx.x;
    const int tx = tid % 16;
    const int ty = tid / 16;

    const float* Ab = A  + (size_t)blockIdx.y * BM * K;
    const float* Bb = Bm + (size_t)blockIdx.x * BN * K;

    const int lrow  = tid >> 1;        // 0..127
    const int lcol4 = (tid & 1) * 4;   // 0 or 4

    float acc[TM][TN];
    #pragma unroll
    for (int i = 0; i < TM; i++)
        #pragma unroll
        for (int j = 0; j < TN; j++) acc[i][j] = 0.0f;

    for (int k0 = 0; k0 < K; k0 += BK) {
        float4 av = *(const float4*)(Ab + (size_t)lrow * K + k0 + lcol4);
        float4 bv = *(const float4*)(Bb + (size_t)lrow * K + k0 + lcol4);
        As[lcol4 + 0][lrow] = av.x; As[lcol4 + 1][lrow] = av.y;
        As[lcol4 + 2][lrow] = av.z; As[lcol4 + 3][lrow] = av.w;
        Bs[lcol4 + 0][lrow] = bv.x; Bs[lcol4 + 1][lrow] = bv.y;
        Bs[lcol4 + 2][lrow] = bv.z; Bs[lcol4 + 3][lrow] = bv.w;
        __syncthreads();

        #pragma unroll
        for (int k = 0; k < BK; k++) {
            float ra[TM], rb[TN];
            #pragma unroll
            for (int i = 0; i < TM; i++) ra[i] = As[k][ty + 16 * i];
            #pragma unroll
            for (int j = 0; j < TN; j++) rb[j] = Bs[k][tx + 16 * j];
            #pragma unroll
            for (int i = 0; i < TM; i++)
                #pragma unroll
                for (int j = 0; j < TN; j++)
                    acc[i][j] = fmaf(ra[i], rb[j], acc[i][j]);
        }
        __syncthreads();
    }

    const int row0 = blockIdx.y * BM;
    const int col0 = blockIdx.x * BN;
    #pragma unroll
    for (int i = 0; i < TM; i++) {
        int r = row0 + ty + 16 * i;
        #pragma unroll
        for (int j = 0; j < TN; j++) {
            int c = col0 + tx + 16 * j;
            C[(size_t)r * N + c] = acc[i][j];
        }
    }
}

// ---------------- Flash attention (fp32) ----------------
// grid: (S/64, B*H); block 256. Each block: 64 Q rows, stream 64-row K/V tiles.
#define TQ 64
#define TK 64
#define PAD 1
#define LDA (DK_ + PAD)   // 65
#define LDP (TK + PAD)    // 65

__global__ __launch_bounds__(256)
void flash_attn(const float* __restrict__ qkv, const unsigned char* __restrict__ mask,
                float* __restrict__ ctx)
{
    extern __shared__ float smem[];
    float* Qs = smem;                      // [TQ][LDA]
    float* Ks = Qs + TQ * LDA;             // [TK][LDA]
    float* Vs = Ks + TK * LDA;             // [TK][LDA]
    float* Ps = Vs + TK * LDA;             // [TQ][LDP]
    float* Ms = Ps + TQ * LDP;             // [TK]

    const int tid = threadIdx.x;
    const int tx = tid % 16;
    const int ty = tid / 16;

    const int bh = blockIdx.y;
    const int b  = bh / H_;
    const int h  = bh % H_;
    const int q0 = blockIdx.x * TQ;

    const size_t row_stride = 3 * D_;
    const float* qbase = qkv + ((size_t)b * S_) * row_stride + (size_t)h * DK_;

    // load Q tile
    for (int idx = tid; idx < TQ * DK_; idx += 256) {
        int r = idx / DK_, c = idx % DK_;
        Qs[r * LDA + c] = qbase[(size_t)(q0 + r) * row_stride + c];
    }

    float m_i[4], l_i[4], acc[4][4];
    #pragma unroll
    for (int i = 0; i < 4; i++) {
        m_i[i] = -INFINITY; l_i[i] = 0.0f;
        #pragma unroll
        for (int j = 0; j < 4; j++) acc[i][j] = 0.0f;
    }

    for (int kt = 0; kt < S_ / TK; kt++) {
        const int k0 = kt * TK;
        __syncthreads();   // prior PV reads of Ks/Vs done
        for (int idx = tid; idx < TK * DK_; idx += 256) {
            int r = idx / DK_, c = idx % DK_;
            size_t g = (size_t)(k0 + r) * row_stride + c;
            Ks[r * LDA + c] = qbase[g + D_];
            Vs[r * LDA + c] = qbase[g + 2 * D_];
        }
        if (tid < TK) Ms[tid] = mask[(size_t)b * S_ + k0 + tid] ? 1.0f : 0.0f;
        __syncthreads();

        // S = Q K^T  (4x4 per thread; rows ty+16i, cols tx+16j)
        float s[4][4];
        #pragma unroll
        for (int i = 0; i < 4; i++)
            #pragma unroll
            for (int j = 0; j < 4; j++) s[i][j] = 0.0f;

        #pragma unroll 4
        for (int kk = 0; kk < DK_; kk++) {
            float qa[4], kb[4];
            #pragma unroll
            for (int i = 0; i < 4; i++) qa[i] = Qs[(ty + 16 * i) * LDA + kk];
            #pragma unroll
            for (int j = 0; j < 4; j++) kb[j] = Ks[(tx + 16 * j) * LDA + kk];
            #pragma unroll
            for (int i = 0; i < 4; i++)
                #pragma unroll
                for (int j = 0; j < 4; j++)
                    s[i][j] = fmaf(qa[i], kb[j], s[i][j]);
        }

        // scale + mask + online softmax per row
        #pragma unroll
        for (int i = 0; i < 4; i++) {
            float rowmax = -INFINITY;
            #pragma unroll
            for (int j = 0; j < 4; j++) {
                float v = (Ms[tx + 16 * j] > 0.0f) ? NEG_ : s[i][j] * SCALE_;
                s[i][j] = v;
                rowmax = fmaxf(rowmax, v);
            }
            #pragma unroll
            for (int off = 8; off >= 1; off >>= 1)
                rowmax = fmaxf(rowmax, __shfl_xor_sync(0xffffffffu, rowmax, off));

            float mnew = fmaxf(m_i[i], rowmax);
            float corr = __expf(m_i[i] - mnew);
            float rowsum = 0.0f;
            #pragma unroll
            for (int j = 0; j < 4; j++) {
                float p = __expf(s[i][j] - mnew);
                Ps[(ty + 16 * i) * LDP + (tx + 16 * j)] = p;
                rowsum += p;
            }
            #pragma unroll
            for (int off = 8; off >= 1; off >>= 1)
                rowsum += __shfl_xor_sync(0xffffffffu, rowsum, off);

            l_i[i] = l_i[i] * corr + rowsum;
            m_i[i] = mnew;
            #pragma unroll
            for (int j = 0; j < 4; j++) acc[i][j] *= corr;
        }
        __syncthreads();   // Ps complete

        // O += P V   (rows ty+16i of P, cols tx+16j of V)
        #pragma unroll 4
        for (int kk = 0; kk < TK; kk++) {
            float pa[4], vb[4];
            #pragma unroll
            for (int i = 0; i < 4; i++) pa[i] = Ps[(ty + 16 * i) * LDP + kk];
            #pragma unroll
            for (int j = 0; j < 4; j++) vb[j] = Vs[kk * LDA + (tx + 16 * j)];
            #pragma unroll
            for (int i = 0; i < 4; i++)
                #pragma unroll
                for (int j = 0; j < 4; j++)
                    acc[i][j] = fmaf(pa[i], vb[j], acc[i][j]);
        }
    }

    // epilogue: ctx[b, q0+row, h*DK + col] = acc / l
    #pragma unroll
    for (int i = 0; i < 4; i++) {
        float inv_l = 1.0f / l_i[i];
        int r = q0 + ty + 16 * i;
        #pragma unroll
        for (int j = 0; j < 4; j++) {
            int c = h * DK_ + tx + 16 * j;
            ctx[((size_t)b * S_ + r) * D_ + c] = acc[i][j] * inv_l;
        }
    }
}

// ---------------- launch ----------------
extern "C" void kernel_launch(void* const* d_in, const int* in_sizes, int n_in,
                              void* d_out, int out_size)
{
    const float* x    = (const float*)d_in[0];
    const float* Wqkv = (const float*)d_in[1];
    const float* Wout = (const float*)d_in[2];
    const unsigned char* mask = (const unsigned char*)d_in[3];
    float* out = (float*)d_out;

    float* qkv = nullptr;
    float* ctx = nullptr;
    cudaGetSymbolAddress((void**)&qkv, g_qkv);
    cudaGetSymbolAddress((void**)&ctx, g_ctx);

    // 1) qkv = x @ Wqkv^T : M=4096, N=3072, K=1024
    {
        dim3 grid((3 * D_) / BN, (B_ * S_) / BM);
        sgemm_abt<<<grid, 256>>>(x, Wqkv, qkv, B_ * S_, 3 * D_, D_);
    }

    // 2) flash attention -> ctx [B,S,D]
    {
        static int smem_set = 0;
        int smem_bytes = (TQ * LDA + 2 * TK * LDA + TQ * LDP + TK) * (int)sizeof(float);
        if (!smem_set) {
            cudaFuncSetAttribute(flash_attn, cudaFuncAttributeMaxDynamicSharedMemorySize, smem_bytes);
            smem_set = 1;
        }
        dim3 grid(S_ / TQ, B_ * H_);
        flash_attn<<<grid, 256, smem_bytes>>>(qkv, mask, ctx);
    }

    // 3) out = ctx @ Wout^T : M=4096, N=1024, K=1024
    {
        dim3 grid(D_ / BN, (B_ * S_) / BM);
        sgemm_abt<<<grid, 256>>>(ctx, Wout, out, B_ * S_, D_, D_);
    }
}

// round 3
// speedup vs baseline: 3.3964x; 3.3964x over previous
#include <cuda_runtime.h>
#include <cuda_bf16.h>
#include <math.h>
#include <stdint.h>

#define B_  2
#define S_  2048
#define D_  1024
#define H_  16
#define DK_ 64
#define SCALE_ 0.125f
#define LOG2E_ 1.44269504f
#define TNEG_ (-86562.0f)   // -60000 * log2(e)

// ---------------- scratch (device globals; no allocation allowed) ----------------
__device__ __nv_bfloat16 g_xh[B_ * S_ * D_];
__device__ __nv_bfloat16 g_xl[B_ * S_ * D_];
__device__ __nv_bfloat16 g_wqkvh[3 * D_ * D_];
__device__ __nv_bfloat16 g_wqkvl[3 * D_ * D_];
__device__ __nv_bfloat16 g_wouth[D_ * D_];
__device__ __nv_bfloat16 g_woutl[D_ * D_];
__device__ __nv_bfloat16 g_qkvh[B_ * S_ * 3 * D_];
__device__ __nv_bfloat16 g_qkvl[B_ * S_ * 3 * D_];
__device__ __nv_bfloat16 g_ctxh[B_ * S_ * D_];
__device__ __nv_bfloat16 g_ctxl[B_ * S_ * D_];

// ================= helpers =================
__device__ __forceinline__ uint32_t smem_u32(const void* p) {
    uint32_t a;
    asm("{ .reg .u64 t; cvta.to.shared.u64 t, %1; cvt.u32.u64 %0, t; }" : "=r"(a) : "l"(p));
    return a;
}
#define CP16(dst, src) asm volatile("cp.async.cg.shared.global [%0], [%1], 16;" :: "r"(dst), "l"(src) : "memory")
#define CP_COMMIT()    asm volatile("cp.async.commit_group;" ::: "memory")
#define CP_WAIT0()     asm volatile("cp.async.wait_group 0;" ::: "memory")

__device__ __forceinline__ void ldsm4(uint32_t* r, uint32_t addr) {
    asm volatile("ldmatrix.sync.aligned.m8n8.x4.shared.b16 {%0,%1,%2,%3}, [%4];"
        : "=r"(r[0]), "=r"(r[1]), "=r"(r[2]), "=r"(r[3]) : "r"(addr));
}
__device__ __forceinline__ void ldsm4t(uint32_t* r, uint32_t addr) {
    asm volatile("ldmatrix.sync.aligned.m8n8.x4.trans.shared.b16 {%0,%1,%2,%3}, [%4];"
        : "=r"(r[0]), "=r"(r[1]), "=r"(r[2]), "=r"(r[3]) : "r"(addr));
}
__device__ __forceinline__ void mma16816(float* d, const uint32_t* a, const uint32_t* b) {
    asm volatile("mma.sync.aligned.m16n8k16.row.col.f32.bf16.bf16.f32 "
        "{%0,%1,%2,%3}, {%4,%5,%6,%7}, {%8,%9}, {%0,%1,%2,%3};"
        : "+f"(d[0]), "+f"(d[1]), "+f"(d[2]), "+f"(d[3])
        : "r"(a[0]), "r"(a[1]), "r"(a[2]), "r"(a[3]), "r"(b[0]), "r"(b[1]));
}
__device__ __forceinline__ float ex2(float x) {
    float y; asm("ex2.approx.ftz.f32 %0, %1;" : "=f"(y) : "f"(x)); return y;
}
// pack two floats into bf16x2 hi + bf16x2 lo (residual)
__device__ __forceinline__ void split2(float a, float b, uint32_t& hi, uint32_t& lo) {
    __nv_bfloat16 ha = __float2bfloat16(a), hb = __float2bfloat16(b);
    hi = (uint32_t)__bfloat16_as_ushort(ha) | ((uint32_t)__bfloat16_as_ushort(hb) << 16);
    __nv_bfloat16 la = __float2bfloat16(a - __bfloat162float(ha));
    __nv_bfloat16 lb = __float2bfloat16(b - __bfloat162float(hb));
    lo = (uint32_t)__bfloat16_as_ushort(la) | ((uint32_t)__bfloat16_as_ushort(lb) << 16);
}

// ================= split fp32 -> bf16 hi/lo =================
__global__ void split_bf16(const float* __restrict__ in, __nv_bfloat16* __restrict__ hi,
                           __nv_bfloat16* __restrict__ lo, int n4) {
    int i = blockIdx.x * blockDim.x + threadIdx.x;
    if (i >= n4) return;
    float4 v = ((const float4*)in)[i];
    uint32_t h0, l0, h1, l1;
    split2(v.x, v.y, h0, l0);
    split2(v.z, v.w, h1, l1);
    ((uint2*)hi)[i] = make_uint2(h0, h1);
    ((uint2*)lo)[i] = make_uint2(l0, l1);
}

// ================= warp-MMA split-bf16 GEMM =================
// C[M,N] = (Ah+Al)[M,K] x (Bh+Bl)[N,K]^T, fp32 accum. 128x128 CTA, BK=64.
// smem tile: [128 rows][stride 144B] (72 bf16), conflict-free for ldmatrix.
#define GSTRIDE_B 144
#define GTILE_B (128 * GSTRIDE_B)       // 18432
#define GSTAGE_B (4 * GTILE_B)          // Ah,Al,Bh,Bl

__global__ __launch_bounds__(256)
void gemm_mma(const __nv_bfloat16* __restrict__ Ah, const __nv_bfloat16* __restrict__ Al,
              const __nv_bfloat16* __restrict__ Bh, const __nv_bfloat16* __restrict__ Bl,
              float* __restrict__ Cf, __nv_bfloat16* __restrict__ Ch, __nv_bfloat16* __restrict__ Cl,
              int N, int K, int split_out)
{
    extern __shared__ char sm[];
    const int tid = threadIdx.x, wid = tid >> 5, lane = tid & 31;
    const int wm = wid & 3, wn = wid >> 2;   // warp grid 4(m) x 2(n): 32 rows x 64 cols per warp
    uint32_t sbase = smem_u32(sm);

    const char* gt[4];
    gt[0] = (const char*)(Ah + (size_t)blockIdx.y * 128 * K);
    gt[1] = (const char*)(Al + (size_t)blockIdx.y * 128 * K);
    gt[2] = (const char*)(Bh + (size_t)blockIdx.x * 128 * K);
    gt[3] = (const char*)(Bl + (size_t)blockIdx.x * 128 * K);

    float acc[2][8][4] = {};

    auto load_stage = [&](int j) {
        uint32_t sb = sbase + (j & 1) * GSTAGE_B;
        #pragma unroll
        for (int t = 0; t < 4; t++) {
            const char* g = gt[t] + (size_t)j * 128;   // j*64 bf16 = 128 bytes
            #pragma unroll
            for (int i = 0; i < 4; i++) {
                int c = tid + i * 256;                 // 1024 chunks per tile
                int row = c >> 3, col = c & 7;
                CP16(sb + t * GTILE_B + row * GSTRIDE_B + col * 16,
                     g + (size_t)row * K * 2 + col * 16);
            }
        }
    };

    load_stage(0); CP_COMMIT();
    const int NK = K / 64;

    for (int j = 0; j < NK; j++) {
        CP_WAIT0();
        __syncthreads();
        if (j + 1 < NK) { load_stage(j + 1); CP_COMMIT(); }

        uint32_t sb = sbase + (j & 1) * GSTAGE_B;
        uint32_t aH = sb + wm * 32 * GSTRIDE_B;
        uint32_t aL = aH + GTILE_B;
        uint32_t bH = sb + 2 * GTILE_B + wn * 64 * GSTRIDE_B;
        uint32_t bL = bH + GTILE_B;
        uint32_t arow = (lane & 15), acs = (lane >> 4) * 16;
        uint32_t brow = (lane & 7) + (lane >> 4) * 8, bcs = ((lane >> 3) & 1) * 16;

        #pragma unroll
        for (int ks = 0; ks < 4; ks++) {
            uint32_t ah[2][4], al[2][4], kbh[4][4], kbl[4][4];
            #pragma unroll
            for (int mt = 0; mt < 2; mt++) {
                ldsm4(ah[mt], aH + (mt * 16 + arow) * GSTRIDE_B + ks * 32 + acs);
                ldsm4(al[mt], aL + (mt * 16 + arow) * GSTRIDE_B + ks * 32 + acs);
            }
            #pragma unroll
            for (int np = 0; np < 4; np++) {
                ldsm4(kbh[np], bH + (np * 16 + brow) * GSTRIDE_B + ks * 32 + bcs);
                ldsm4(kbl[np], bL + (np * 16 + brow) * GSTRIDE_B + ks * 32 + bcs);
            }
            #pragma unroll
            for (int mt = 0; mt < 2; mt++)
                #pragma unroll
                for (int np = 0; np < 4; np++) {
                    mma16816(acc[mt][2 * np],     ah[mt], &kbh[np][0]);
                    mma16816(acc[mt][2 * np + 1], ah[mt], &kbh[np][2]);
                    mma16816(acc[mt][2 * np],     ah[mt], &kbl[np][0]);
                    mma16816(acc[mt][2 * np + 1], ah[mt], &kbl[np][2]);
                    mma16816(acc[mt][2 * np],     al[mt], &kbh[np][0]);
                    mma16816(acc[mt][2 * np + 1], al[mt], &kbh[np][2]);
                }
        }
    }

    const int rb = blockIdx.y * 128 + wm * 32 + (lane >> 2);
    const int cb = blockIdx.x * 128 + wn * 64 + (lane & 3) * 2;
    #pragma unroll
    for (int mt = 0; mt < 2; mt++)
        #pragma unroll
        for (int half = 0; half < 2; half++) {
            int r = rb + mt * 16 + half * 8;
            #pragma unroll
            for (int nt = 0; nt < 8; nt++) {
                int c = cb + nt * 8;
                float v0 = acc[mt][nt][half * 2 + 0];
                float v1 = acc[mt][nt][half * 2 + 1];
                if (split_out) {
                    uint32_t hi, lo;
                    split2(v0, v1, hi, lo);
                    *(uint32_t*)(Ch + (size_t)r * N + c) = hi;
                    *(uint32_t*)(Cl + (size_t)r * N + c) = lo;
                } else {
                    *(float2*)(Cf + (size_t)r * N + c) = make_float2(v0, v1);
                }
            }
        }
}

// ================= flash attention, warp-MMA split-bf16 =================
// CTA: 64 Q rows of one (b,h), 4 warps (warp w -> rows w*16..+15), TK=64 stream.
#define FTILE_B (64 * GSTRIDE_B)        // 9216
#define FSTAGE_B (4 * FTILE_B)          // Kh,Kl,Vh,Vl
#define FQ_OFF 0
#define FST_OFF (2 * FTILE_B)           // after Qh,Ql
#define FMS_OFF (FST_OFF + 2 * FSTAGE_B)
#define FSMEM_TOTAL (FMS_OFF + 128)

__global__ __launch_bounds__(128)
void flash_mma(const __nv_bfloat16* __restrict__ qh, const __nv_bfloat16* __restrict__ ql,
               const unsigned char* __restrict__ mask,
               __nv_bfloat16* __restrict__ cth, __nv_bfloat16* __restrict__ ctl)
{
    extern __shared__ char sm[];
    const int tid = threadIdx.x, wid = tid >> 5, lane = tid & 31;
    const int bh = blockIdx.y, b = bh >> 4, h = bh & 15;
    const int q0 = blockIdx.x * 64;
    uint32_t sbase = smem_u32(sm);
    const uint32_t QH = sbase + FQ_OFF, QL = QH + FTILE_B;
    const uint32_t STG = sbase + FST_OFF;

    const size_t rs = 3 * D_;   // qkv row stride (elems)
    const char* qbh = (const char*)(qh + ((size_t)b * S_ + q0) * rs + h * 64);
    const char* qbl = (const char*)(ql + ((size_t)b * S_ + q0) * rs + h * 64);
    const char* kbh = (const char*)(qh + (size_t)b * S_ * rs + D_ + h * 64);
    const char* kbl = (const char*)(ql + (size_t)b * S_ * rs + D_ + h * 64);
    const char* vbh = (const char*)(qh + (size_t)b * S_ * rs + 2 * D_ + h * 64);
    const char* vbl = (const char*)(ql + (size_t)b * S_ * rs + 2 * D_ + h * 64);

    auto load_kv = [&](int j) {
        uint32_t sb = STG + (j & 1) * FSTAGE_B;
        size_t gk = (size_t)j * 64 * rs * 2;
        #pragma unroll
        for (int i = 0; i < 4; i++) {
            int c = tid + i * 128;                 // 512 chunks per buf
            int row = c >> 3, col = c & 7;
            size_t go = gk + (size_t)row * rs * 2 + col * 16;
            uint32_t so = row * GSTRIDE_B + col * 16;
            CP16(sb + 0 * FTILE_B + so, kbh + go);
            CP16(sb + 1 * FTILE_B + so, kbl + go);
            CP16(sb + 2 * FTILE_B + so, vbh + go);
            CP16(sb + 3 * FTILE_B + so, vbl + go);
        }
    };
    auto store_mask = [&](int j) {
        if (tid < 16) {
            uint32_t v = *(const uint32_t*)(mask + (size_t)b * S_ + j * 64 + tid * 4);
            *(uint32_t*)(sm + FMS_OFF + (j & 1) * 64 + tid * 4) = v;
        }
    };

    // load Q + stage 0
    #pragma unroll
    for (int i = 0; i < 4; i++) {
        int c = tid + i * 128;
        int row = c >> 3, col = c & 7;
        uint32_t so = row * GSTRIDE_B + col * 16;
        CP16(QH + so, qbh + (size_t)row * rs * 2 + col * 16);
        CP16(QL + so, qbl + (size_t)row * rs * 2 + col * 16);
    }
    load_kv(0); CP_COMMIT();
    store_mask(0);

    uint32_t qfh[4][4], qfl[4][4];
    float o[8][4] = {};
    float m0 = -1e30f, m1 = -1e30f, l0 = 0.0f, l1 = 0.0f;

    const uint32_t arow = (lane & 15), acs = (lane >> 4) * 16;
    const uint32_t brow = (lane & 7) + (lane >> 4) * 8, bcs = ((lane >> 3) & 1) * 16;

    for (int kt = 0; kt < S_ / 64; kt++) {
        CP_WAIT0();
        __syncthreads();
        if (kt == 0) {
            #pragma unroll
            for (int ks = 0; ks < 4; ks++) {
                ldsm4(qfh[ks], QH + (wid * 16 + arow) * GSTRIDE_B + ks * 32 + acs);
                ldsm4(qfl[ks], QL + (wid * 16 + arow) * GSTRIDE_B + ks * 32 + acs);
            }
        }
        if (kt + 1 < S_ / 64) { load_kv(kt + 1); CP_COMMIT(); store_mask(kt + 1); }

        uint32_t sb = STG + (kt & 1) * FSTAGE_B;
        uint32_t KH = sb, KL = sb + FTILE_B, VH = sb + 2 * FTILE_B, VL = sb + 3 * FTILE_B;

        // ---- S = Q K^T (3-term) ----
        float s[8][4] = {};
        #pragma unroll
        for (int ks = 0; ks < 4; ks++) {
            uint32_t kh[4][4], kl[4][4];
            #pragma unroll
            for (int np = 0; np < 4; np++) {
                ldsm4(kh[np], KH + (np * 16 + brow) * GSTRIDE_B + ks * 32 + bcs);
                ldsm4(kl[np], KL + (np * 16 + brow) * GSTRIDE_B + ks * 32 + bcs);
            }
            #pragma unroll
            for (int np = 0; np < 4; np++) {
                mma16816(s[2 * np],     qfh[ks], &kh[np][0]);
                mma16816(s[2 * np + 1], qfh[ks], &kh[np][2]);
                mma16816(s[2 * np],     qfh[ks], &kl[np][0]);
                mma16816(s[2 * np + 1], qfh[ks], &kl[np][2]);
                mma16816(s[2 * np],     qfl[ks], &kh[np][0]);
                mma16816(s[2 * np + 1], qfl[ks], &kh[np][2]);
            }
        }

        // ---- softmax (exp2 domain) ----
        const float CM = SCALE_ * LOG2E_;
        float rmax0 = -1e30f, rmax1 = -1e30f;
        #pragma unroll
        for (int nt = 0; nt < 8; nt++) {
            unsigned short mm = *(const unsigned short*)(sm + FMS_OFF + (kt & 1) * 64 + nt * 8 + (lane & 3) * 2);
            bool k0m = (mm & 0xFF) != 0, k1m = (mm >> 8) != 0;
            s[nt][0] = k0m ? TNEG_ : s[nt][0] * CM;
            s[nt][1] = k1m ? TNEG_ : s[nt][1] * CM;
            s[nt][2] = k0m ? TNEG_ : s[nt][2] * CM;
            s[nt][3] = k1m ? TNEG_ : s[nt][3] * CM;
            rmax0 = fmaxf(rmax0, fmaxf(s[nt][0], s[nt][1]));
            rmax1 = fmaxf(rmax1, fmaxf(s[nt][2], s[nt][3]));
        }
        rmax0 = fmaxf(rmax0, __shfl_xor_sync(0xffffffffu, rmax0, 1));
        rmax0 = fmaxf(rmax0, __shfl_xor_sync(0xffffffffu, rmax0, 2));
        rmax1 = fmaxf(rmax1, __shfl_xor_sync(0xffffffffu, rmax1, 1));
        rmax1 = fmaxf(rmax1, __shfl_xor_sync(0xffffffffu, rmax1, 2));
        float mn0 = fmaxf(m0, rmax0), mn1 = fmaxf(m1, rmax1);
        float cr0 = ex2(m0 - mn0), cr1 = ex2(m1 - mn1);
        m0 = mn0; m1 = mn1;
        float ps0 = 0.0f, ps1 = 0.0f;
        #pragma unroll
        for (int nt = 0; nt < 8; nt++) {
            s[nt][0] = ex2(s[nt][0] - mn0);
            s[nt][1] = ex2(s[nt][1] - mn0);
            s[nt][2] = ex2(s[nt][2] - mn1);
            s[nt][3] = ex2(s[nt][3] - mn1);
            ps0 += s[nt][0] + s[nt][1];
            ps1 += s[nt][2] + s[nt][3];
        }
        ps0 += __shfl_xor_sync(0xffffffffu, ps0, 1);
        ps0 += __shfl_xor_sync(0xffffffffu, ps0, 2);
        ps1 += __shfl_xor_sync(0xffffffffu, ps1, 1);
        ps1 += __shfl_xor_sync(0xffffffffu, ps1, 2);
        l0 = l0 * cr0 + ps0;
        l1 = l1 * cr1 + ps1;
        #pragma unroll
        for (int nt = 0; nt < 8; nt++) {
            o[nt][0] *= cr0; o[nt][1] *= cr0;
            o[nt][2] *= cr1; o[nt][3] *= cr1;
        }

        // P -> bf16 hi/lo A-fragments
        uint32_t ph[4][4], pl[4][4];
        #pragma unroll
        for (int kp = 0; kp < 4; kp++) {
            split2(s[2 * kp][0],     s[2 * kp][1],     ph[kp][0], pl[kp][0]);
            split2(s[2 * kp][2],     s[2 * kp][3],     ph[kp][1], pl[kp][1]);
            split2(s[2 * kp + 1][0], s[2 * kp + 1][1], ph[kp][2], pl[kp][2]);
            split2(s[2 * kp + 1][2], s[2 * kp + 1][3], ph[kp][3], pl[kp][3]);
        }

        // ---- O += P V (3-term) ----
        #pragma unroll
        for (int kp = 0; kp < 4; kp++) {
            uint32_t vh[4][4], vl[4][4];
            uint32_t krow = kp * 16 + (lane & 15);
            uint32_t dbyte = (lane >> 4) * 16;
            #pragma unroll
            for (int dp = 0; dp < 4; dp++) {
                ldsm4t(vh[dp], VH + krow * GSTRIDE_B + dp * 32 + dbyte);
                ldsm4t(vl[dp], VL + krow * GSTRIDE_B + dp * 32 + dbyte);
            }
            #pragma unroll
            for (int dp = 0; dp < 4; dp++) {
                mma16816(o[2 * dp],     ph[kp], &vh[dp][0]);
                mma16816(o[2 * dp + 1], ph[kp], &vh[dp][2]);
                mma16816(o[2 * dp],     ph[kp], &vl[dp][0]);
                mma16816(o[2 * dp + 1], ph[kp], &vl[dp][2]);
                mma16816(o[2 * dp],     pl[kp], &vh[dp][0]);
                mma16816(o[2 * dp + 1], pl[kp], &vh[dp][2]);
            }
        }
    }

    // epilogue: ctx hi/lo
    float il0 = 1.0f / l0, il1 = 1.0f / l1;
    int r0 = q0 + wid * 16 + (lane >> 2);
    int cbase = h * 64 + (lane & 3) * 2;
    #pragma unroll
    for (int nt = 0; nt < 8; nt++) {
        int c = cbase + nt * 8;
        uint32_t hi, lo;
        size_t i0 = ((size_t)b * S_ + r0) * D_ + c;
        split2(o[nt][0] * il0, o[nt][1] * il0, hi, lo);
        *(uint32_t*)(cth + i0) = hi;
        *(uint32_t*)(ctl + i0) = lo;
        size_t i1 = i0 + 8 * D_;
        split2(o[nt][2] * il1, o[nt][3] * il1, hi, lo);
        *(uint32_t*)(cth + i1) = hi;
        *(uint32_t*)(ctl + i1) = lo;
    }
}

// ---------------- launch ----------------
extern "C" void kernel_launch(void* const* d_in, const int* in_sizes, int n_in,
                              void* d_out, int out_size)
{
    const float* x    = (const float*)d_in[0];
    const float* Wqkv = (const float*)d_in[1];
    const float* Wout = (const float*)d_in[2];
    const unsigned char* mask = (const unsigned char*)d_in[3];
    float* out = (float*)d_out;

    __nv_bfloat16 *xh, *xl, *wqh, *wql, *woh, *wol, *qvh, *qvl, *cth, *ctl;
    cudaGetSymbolAddress((void**)&xh,  g_xh);
    cudaGetSymbolAddress((void**)&xl,  g_xl);
    cudaGetSymbolAddress((void**)&wqh, g_wqkvh);
    cudaGetSymbolAddress((void**)&wql, g_wqkvl);
    cudaGetSymbolAddress((void**)&woh, g_wouth);
    cudaGetSymbolAddress((void**)&wol, g_woutl);
    cudaGetSymbolAddress((void**)&qvh, g_qkvh);
    cudaGetSymbolAddress((void**)&qvl, g_qkvl);
    cudaGetSymbolAddress((void**)&cth, g_ctxh);
    cudaGetSymbolAddress((void**)&ctl, g_ctxl);

    const int gemm_smem = 2 * GSTAGE_B;     // 147456
    const int flash_smem = FSMEM_TOTAL;     // 92288
    static int attrs_set = 0;
    if (!attrs_set) {
        cudaFuncSetAttribute(gemm_mma, cudaFuncAttributeMaxDynamicSharedMemorySize, gemm_smem);
        cudaFuncSetAttribute(flash_mma, cudaFuncAttributeMaxDynamicSharedMemorySize, flash_smem);
        attrs_set = 1;
    }

    // 0) split inputs
    {
        int n4x = (B_ * S_ * D_) / 4;
        split_bf16<<<(n4x + 255) / 256, 256>>>(x, xh, xl, n4x);
        int n4w = (3 * D_ * D_) / 4;
        split_bf16<<<(n4w + 255) / 256, 256>>>(Wqkv, wqh, wql, n4w);
        int n4o = (D_ * D_) / 4;
        split_bf16<<<(n4o + 255) / 256, 256>>>(Wout, woh, wol, n4o);
    }

    // 1) qkv = x @ Wqkv^T -> bf16 hi/lo   (M=4096, N=3072, K=1024)
    {
        dim3 grid((3 * D_) / 128, (B_ * S_) / 128);
        gemm_mma<<<grid, 256, gemm_smem>>>(xh, xl, wqh, wql, nullptr, qvh, qvl, 3 * D_, D_, 1);
    }

    // 2) flash attention -> ctx hi/lo
    {
        dim3 grid(S_ / 64, B_ * H_);
        flash_mma<<<grid, 128, flash_smem>>>(qvh, qvl, mask, cth, ctl);
    }

    // 3) out = ctx @ Wout^T -> f32   (M=4096, N=1024, K=1024)
    {
        dim3 grid(D_ / 128, (B_ * S_) / 128);
        gemm_mma<<<grid, 256, gemm_smem>>>(cth, ctl, woh, wol, out, nullptr, nullptr, D_, D_, 0);
    }
}

// round 4
// speedup vs baseline: 3.4522x; 1.0164x over previous
#include <cuda_runtime.h>
#include <cuda_bf16.h>
#include <math.h>
#include <stdint.h>

#define B_  2
#define S_  2048
#define D_  1024
#define H_  16
#define DK_ 64
#define SCALE_ 0.125f
#define LOG2E_ 1.44269504f
#define TNEG_ (-86562.0f)   // -60000 * log2(e)

// ---------------- scratch (device globals; no allocation allowed) ----------------
__device__ __nv_bfloat16 g_xh[B_ * S_ * D_];
__device__ __nv_bfloat16 g_xl[B_ * S_ * D_];
__device__ __nv_bfloat16 g_wqkvh[3 * D_ * D_];
__device__ __nv_bfloat16 g_wqkvl[3 * D_ * D_];
__device__ __nv_bfloat16 g_wouth[D_ * D_];
__device__ __nv_bfloat16 g_woutl[D_ * D_];
__device__ __nv_bfloat16 g_qkvh[B_ * S_ * 3 * D_];
__device__ __nv_bfloat16 g_qkvl[B_ * S_ * 3 * D_];
__device__ __nv_bfloat16 g_ctxh[B_ * S_ * D_];
__device__ __nv_bfloat16 g_ctxl[B_ * S_ * D_];

// ================= helpers =================
__device__ __forceinline__ uint32_t smem_u32(const void* p) {
    uint32_t a;
    asm("{ .reg .u64 t; cvta.to.shared.u64 t, %1; cvt.u32.u64 %0, t; }" : "=r"(a) : "l"(p));
    return a;
}
#define CP16(dst, src) asm volatile("cp.async.cg.shared.global [%0], [%1], 16;" :: "r"(dst), "l"(src) : "memory")
#define CP_COMMIT()    asm volatile("cp.async.commit_group;" ::: "memory")
#define CP_WAIT0()     asm volatile("cp.async.wait_group 0;" ::: "memory")

__device__ __forceinline__ void ldsm4(uint32_t* r, uint32_t addr) {
    asm volatile("ldmatrix.sync.aligned.m8n8.x4.shared.b16 {%0,%1,%2,%3}, [%4];"
        : "=r"(r[0]), "=r"(r[1]), "=r"(r[2]), "=r"(r[3]) : "r"(addr));
}
__device__ __forceinline__ void ldsm4t(uint32_t* r, uint32_t addr) {
    asm volatile("ldmatrix.sync.aligned.m8n8.x4.trans.shared.b16 {%0,%1,%2,%3}, [%4];"
        : "=r"(r[0]), "=r"(r[1]), "=r"(r[2]), "=r"(r[3]) : "r"(addr));
}
__device__ __forceinline__ void mma16816(float* d, const uint32_t* a, const uint32_t* b) {
    asm volatile("mma.sync.aligned.m16n8k16.row.col.f32.bf16.bf16.f32 "
        "{%0,%1,%2,%3}, {%4,%5,%6,%7}, {%8,%9}, {%0,%1,%2,%3};"
        : "+f"(d[0]), "+f"(d[1]), "+f"(d[2]), "+f"(d[3])
        : "r"(a[0]), "r"(a[1]), "r"(a[2]), "r"(a[3]), "r"(b[0]), "r"(b[1]));
}
__device__ __forceinline__ float ex2(float x) {
    float y; asm("ex2.approx.ftz.f32 %0, %1;" : "=f"(y) : "f"(x)); return y;
}
__device__ __forceinline__ void split2(float a, float b, uint32_t& hi, uint32_t& lo) {
    __nv_bfloat16 ha = __float2bfloat16(a), hb = __float2bfloat16(b);
    hi = (uint32_t)__bfloat16_as_ushort(ha) | ((uint32_t)__bfloat16_as_ushort(hb) << 16);
    __nv_bfloat16 la = __float2bfloat16(a - __bfloat162float(ha));
    __nv_bfloat16 lb = __float2bfloat16(b - __bfloat162float(hb));
    lo = (uint32_t)__bfloat16_as_ushort(la) | ((uint32_t)__bfloat16_as_ushort(lb) << 16);
}

// ================= split fp32 -> bf16 hi/lo =================
__global__ void split_bf16(const float* __restrict__ in, __nv_bfloat16* __restrict__ hi,
                           __nv_bfloat16* __restrict__ lo, int n4) {
    int i = blockIdx.x * blockDim.x + threadIdx.x;
    if (i >= n4) return;
    float4 v = ((const float4*)in)[i];
    uint32_t h0, l0, h1, l1;
    split2(v.x, v.y, h0, l0);
    split2(v.z, v.w, h1, l1);
    ((uint2*)hi)[i] = make_uint2(h0, h1);
    ((uint2*)lo)[i] = make_uint2(l0, l1);
}

// ================= warp-MMA split-bf16 GEMM =================
#define GSTRIDE_B 144
#define GTILE_B (128 * GSTRIDE_B)       // 18432
#define GSTAGE_B (4 * GTILE_B)

__global__ __launch_bounds__(256)
void gemm_mma(const __nv_bfloat16* __restrict__ Ah, const __nv_bfloat16* __restrict__ Al,
              const __nv_bfloat16* __restrict__ Bh, const __nv_bfloat16* __restrict__ Bl,
              float* __restrict__ Cf, __nv_bfloat16* __restrict__ Ch, __nv_bfloat16* __restrict__ Cl,
              int N, int K, int split_out)
{
    extern __shared__ char sm[];
    const int tid = threadIdx.x, wid = tid >> 5, lane = tid & 31;
    const int wm = wid & 3, wn = wid >> 2;   // 4(m) x 2(n): 32 rows x 64 cols per warp
    uint32_t sbase = smem_u32(sm);

    const char* gt[4];
    gt[0] = (const char*)(Ah + (size_t)blockIdx.y * 128 * K);
    gt[1] = (const char*)(Al + (size_t)blockIdx.y * 128 * K);
    gt[2] = (const char*)(Bh + (size_t)blockIdx.x * 128 * K);
    gt[3] = (const char*)(Bl + (size_t)blockIdx.x * 128 * K);

    float acc[2][8][4] = {};

    auto load_stage = [&](int j) {
        uint32_t sb = sbase + (j & 1) * GSTAGE_B;
        #pragma unroll
        for (int t = 0; t < 4; t++) {
            const char* g = gt[t] + (size_t)j * 128;
            #pragma unroll
            for (int i = 0; i < 4; i++) {
                int c = tid + i * 256;
                int row = c >> 3, col = c & 7;
                CP16(sb + t * GTILE_B + row * GSTRIDE_B + col * 16,
                     g + (size_t)row * K * 2 + col * 16);
            }
        }
    };

    load_stage(0); CP_COMMIT();
    const int NK = K / 64;

    for (int j = 0; j < NK; j++) {
        CP_WAIT0();
        __syncthreads();
        if (j + 1 < NK) { load_stage(j + 1); CP_COMMIT(); }

        uint32_t sb = sbase + (j & 1) * GSTAGE_B;
        uint32_t aH = sb + wm * 32 * GSTRIDE_B;
        uint32_t aL = aH + GTILE_B;
        uint32_t bH = sb + 2 * GTILE_B + wn * 64 * GSTRIDE_B;
        uint32_t bL = bH + GTILE_B;
        uint32_t arow = (lane & 15), acs = (lane >> 4) * 16;
        uint32_t brow = (lane & 7) + (lane >> 4) * 8, bcs = ((lane >> 3) & 1) * 16;

        #pragma unroll
        for (int ks = 0; ks < 4; ks++) {
            uint32_t ah[2][4], al[2][4], kbh[4][4], kbl[4][4];
            #pragma unroll
            for (int mt = 0; mt < 2; mt++) {
                ldsm4(ah[mt], aH + (mt * 16 + arow) * GSTRIDE_B + ks * 32 + acs);
                ldsm4(al[mt], aL + (mt * 16 + arow) * GSTRIDE_B + ks * 32 + acs);
            }
            #pragma unroll
            for (int np = 0; np < 4; np++) {
                ldsm4(kbh[np], bH + (np * 16 + brow) * GSTRIDE_B + ks * 32 + bcs);
                ldsm4(kbl[np], bL + (np * 16 + brow) * GSTRIDE_B + ks * 32 + bcs);
            }
            // term-major: 16 independent accumulators per pass
            #pragma unroll
            for (int mt = 0; mt < 2; mt++)
                #pragma unroll
                for (int np = 0; np < 4; np++) {
                    mma16816(acc[mt][2 * np],     ah[mt], &kbh[np][0]);
                    mma16816(acc[mt][2 * np + 1], ah[mt], &kbh[np][2]);
                }
            #pragma unroll
            for (int mt = 0; mt < 2; mt++)
                #pragma unroll
                for (int np = 0; np < 4; np++) {
                    mma16816(acc[mt][2 * np],     ah[mt], &kbl[np][0]);
                    mma16816(acc[mt][2 * np + 1], ah[mt], &kbl[np][2]);
                }
            #pragma unroll
            for (int mt = 0; mt < 2; mt++)
                #pragma unroll
                for (int np = 0; np < 4; np++) {
                    mma16816(acc[mt][2 * np],     al[mt], &kbh[np][0]);
                    mma16816(acc[mt][2 * np + 1], al[mt], &kbh[np][2]);
                }
        }
    }

    const int rb = blockIdx.y * 128 + wm * 32 + (lane >> 2);
    const int cb = blockIdx.x * 128 + wn * 64 + (lane & 3) * 2;
    #pragma unroll
    for (int mt = 0; mt < 2; mt++)
        #pragma unroll
        for (int half = 0; half < 2; half++) {
            int r = rb + mt * 16 + half * 8;
            #pragma unroll
            for (int nt = 0; nt < 8; nt++) {
                int c = cb + nt * 8;
                float v0 = acc[mt][nt][half * 2 + 0];
                float v1 = acc[mt][nt][half * 2 + 1];
                if (split_out) {
                    uint32_t hi, lo;
                    split2(v0, v1, hi, lo);
                    *(uint32_t*)(Ch + (size_t)r * N + c) = hi;
                    *(uint32_t*)(Cl + (size_t)r * N + c) = lo;
                } else {
                    *(float2*)(Cf + (size_t)r * N + c) = make_float2(v0, v1);
                }
            }
        }
}

// ================= flash attention, warp-MMA split-bf16 =================
#define FTILE_B (64 * GSTRIDE_B)        // 9216
#define FSTAGE_B (4 * FTILE_B)
#define FQ_OFF 0
#define FST_OFF (2 * FTILE_B)
#define FMS_OFF (FST_OFF + 2 * FSTAGE_B)
#define FSMEM_TOTAL (FMS_OFF + 128)

__global__ __launch_bounds__(128, 2)
void flash_mma(const __nv_bfloat16* __restrict__ qh, const __nv_bfloat16* __restrict__ ql,
               const unsigned char* __restrict__ mask,
               __nv_bfloat16* __restrict__ cth, __nv_bfloat16* __restrict__ ctl)
{
    extern __shared__ char sm[];
    const int tid = threadIdx.x, wid = tid >> 5, lane = tid & 31;
    const int bh = blockIdx.y, b = bh >> 4, h = bh & 15;
    const int q0 = blockIdx.x * 64;
    uint32_t sbase = smem_u32(sm);
    const uint32_t QH = sbase + FQ_OFF, QL = QH + FTILE_B;
    const uint32_t STG = sbase + FST_OFF;

    const size_t rs = 3 * D_;
    const char* qbh = (const char*)(qh + ((size_t)b * S_ + q0) * rs + h * 64);
    const char* qbl = (const char*)(ql + ((size_t)b * S_ + q0) * rs + h * 64);
    const char* kbh = (const char*)(qh + (size_t)b * S_ * rs + D_ + h * 64);
    const char* kbl = (const char*)(ql + (size_t)b * S_ * rs + D_ + h * 64);
    const char* vbh = (const char*)(qh + (size_t)b * S_ * rs + 2 * D_ + h * 64);
    const char* vbl = (const char*)(ql + (size_t)b * S_ * rs + 2 * D_ + h * 64);

    auto load_kv = [&](int j) {
        uint32_t sb = STG + (j & 1) * FSTAGE_B;
        size_t gk = (size_t)j * 64 * rs * 2;
        #pragma unroll
        for (int i = 0; i < 4; i++) {
            int c = tid + i * 128;
            int row = c >> 3, col = c & 7;
            size_t go = gk + (size_t)row * rs * 2 + col * 16;
            uint32_t so = row * GSTRIDE_B + col * 16;
            CP16(sb + 0 * FTILE_B + so, kbh + go);
            CP16(sb + 1 * FTILE_B + so, kbl + go);
            CP16(sb + 2 * FTILE_B + so, vbh + go);
            CP16(sb + 3 * FTILE_B + so, vbl + go);
        }
    };
    auto store_mask = [&](int j) {
        if (tid < 16) {
            uint32_t v = *(const uint32_t*)(mask + (size_t)b * S_ + j * 64 + tid * 4);
            *(uint32_t*)(sm + FMS_OFF + (j & 1) * 64 + tid * 4) = v;
        }
    };

    #pragma unroll
    for (int i = 0; i < 4; i++) {
        int c = tid + i * 128;
        int row = c >> 3, col = c & 7;
        uint32_t so = row * GSTRIDE_B + col * 16;
        CP16(QH + so, qbh + (size_t)row * rs * 2 + col * 16);
        CP16(QL + so, qbl + (size_t)row * rs * 2 + col * 16);
    }
    load_kv(0); CP_COMMIT();
    store_mask(0);

    uint32_t qfh[4][4], qfl[4][4];
    float o[8][4] = {};
    float m0 = -1e30f, m1 = -1e30f, l0 = 0.0f, l1 = 0.0f;

    const uint32_t arow = (lane & 15), acs = (lane >> 4) * 16;
    const uint32_t brow = (lane & 7) + (lane >> 4) * 8, bcs = ((lane >> 3) & 1) * 16;

    for (int kt = 0; kt < S_ / 64; kt++) {
        CP_WAIT0();
        __syncthreads();
        if (kt == 0) {
            #pragma unroll
            for (int ks = 0; ks < 4; ks++) {
                ldsm4(qfh[ks], QH + (wid * 16 + arow) * GSTRIDE_B + ks * 32 + acs);
                ldsm4(qfl[ks], QL + (wid * 16 + arow) * GSTRIDE_B + ks * 32 + acs);
            }
        }
        if (kt + 1 < S_ / 64) { load_kv(kt + 1); CP_COMMIT(); store_mask(kt + 1); }

        uint32_t sb = STG + (kt & 1) * FSTAGE_B;
        uint32_t KH = sb, KL = sb + FTILE_B, VH = sb + 2 * FTILE_B, VL = sb + 3 * FTILE_B;

        // ---- S = Q K^T (3-term, term-major for acc ILP) ----
        float s[8][4] = {};
        #pragma unroll
        for (int ks = 0; ks < 4; ks++) {
            uint32_t kh[4][4], kl[4][4];
            #pragma unroll
            for (int np = 0; np < 4; np++) {
                ldsm4(kh[np], KH + (np * 16 + brow) * GSTRIDE_B + ks * 32 + bcs);
                ldsm4(kl[np], KL + (np * 16 + brow) * GSTRIDE_B + ks * 32 + bcs);
            }
            #pragma unroll
            for (int np = 0; np < 4; np++) {
                mma16816(s[2 * np],     qfh[ks], &kh[np][0]);
                mma16816(s[2 * np + 1], qfh[ks], &kh[np][2]);
            }
            #pragma unroll
            for (int np = 0; np < 4; np++) {
                mma16816(s[2 * np],     qfh[ks], &kl[np][0]);
                mma16816(s[2 * np + 1], qfh[ks], &kl[np][2]);
            }
            #pragma unroll
            for (int np = 0; np < 4; np++) {
                mma16816(s[2 * np],     qfl[ks], &kh[np][0]);
                mma16816(s[2 * np + 1], qfl[ks], &kh[np][2]);
            }
        }

        // ---- softmax (exp2 domain) ----
        const float CM = SCALE_ * LOG2E_;
        float rmax0 = -1e30f, rmax1 = -1e30f;
        #pragma unroll
        for (int nt = 0; nt < 8; nt++) {
            unsigned short mm = *(const unsigned short*)(sm + FMS_OFF + (kt & 1) * 64 + nt * 8 + (lane & 3) * 2);
            bool k0m = (mm & 0xFF) != 0, k1m = (mm >> 8) != 0;
            s[nt][0] = k0m ? TNEG_ : s[nt][0] * CM;
            s[nt][1] = k1m ? TNEG_ : s[nt][1] * CM;
            s[nt][2] = k0m ? TNEG_ : s[nt][2] * CM;
            s[nt][3] = k1m ? TNEG_ : s[nt][3] * CM;
            rmax0 = fmaxf(rmax0, fmaxf(s[nt][0], s[nt][1]));
            rmax1 = fmaxf(rmax1, fmaxf(s[nt][2], s[nt][3]));
        }
        rmax0 = fmaxf(rmax0, __shfl_xor_sync(0xffffffffu, rmax0, 1));
        rmax0 = fmaxf(rmax0, __shfl_xor_sync(0xffffffffu, rmax0, 2));
        rmax1 = fmaxf(rmax1, __shfl_xor_sync(0xffffffffu, rmax1, 1));
        rmax1 = fmaxf(rmax1, __shfl_xor_sync(0xffffffffu, rmax1, 2));
        float mn0 = fmaxf(m0, rmax0), mn1 = fmaxf(m1, rmax1);
        float cr0 = ex2(m0 - mn0), cr1 = ex2(m1 - mn1);
        m0 = mn0; m1 = mn1;
        float ps0 = 0.0f, ps1 = 0.0f;
        #pragma unroll
        for (int nt = 0; nt < 8; nt++) {
            s[nt][0] = ex2(s[nt][0] - mn0);
            s[nt][1] = ex2(s[nt][1] - mn0);
            s[nt][2] = ex2(s[nt][2] - mn1);
            s[nt][3] = ex2(s[nt][3] - mn1);
            ps0 += s[nt][0] + s[nt][1];
            ps1 += s[nt][2] + s[nt][3];
        }
        ps0 += __shfl_xor_sync(0xffffffffu, ps0, 1);
        ps0 += __shfl_xor_sync(0xffffffffu, ps0, 2);
        ps1 += __shfl_xor_sync(0xffffffffu, ps1, 1);
        ps1 += __shfl_xor_sync(0xffffffffu, ps1, 2);
        l0 = l0 * cr0 + ps0;
        l1 = l1 * cr1 + ps1;
        #pragma unroll
        for (int nt = 0; nt < 8; nt++) {
            o[nt][0] *= cr0; o[nt][1] *= cr0;
            o[nt][2] *= cr1; o[nt][3] *= cr1;
        }

        uint32_t ph[4][4], pl[4][4];
        #pragma unroll
        for (int kp = 0; kp < 4; kp++) {
            split2(s[2 * kp][0],     s[2 * kp][1],     ph[kp][0], pl[kp][0]);
            split2(s[2 * kp][2],     s[2 * kp][3],     ph[kp][1], pl[kp][1]);
            split2(s[2 * kp + 1][0], s[2 * kp + 1][1], ph[kp][2], pl[kp][2]);
            split2(s[2 * kp + 1][2], s[2 * kp + 1][3], ph[kp][3], pl[kp][3]);
        }

        // ---- O += P V (3-term, term-major) ----
        #pragma unroll
        for (int kp = 0; kp < 4; kp++) {
            uint32_t vh[4][4], vl[4][4];
            uint32_t krow = kp * 16 + (lane & 15);
            uint32_t dbyte = (lane >> 4) * 16;
            #pragma unroll
            for (int dp = 0; dp < 4; dp++) {
                ldsm4t(vh[dp], VH + krow * GSTRIDE_B + dp * 32 + dbyte);
                ldsm4t(vl[dp], VL + krow * GSTRIDE_B + dp * 32 + dbyte);
            }
            #pragma unroll
            for (int dp = 0; dp < 4; dp++) {
                mma16816(o[2 * dp],     ph[kp], &vh[dp][0]);
                mma16816(o[2 * dp + 1], ph[kp], &vh[dp][2]);
            }
            #pragma unroll
            for (int dp = 0; dp < 4; dp++) {
                mma16816(o[2 * dp],     ph[kp], &vl[dp][0]);
                mma16816(o[2 * dp + 1], ph[kp], &vl[dp][2]);
            }
            #pragma unroll
            for (int dp = 0; dp < 4; dp++) {
                mma16816(o[2 * dp],     pl[kp], &vh[dp][0]);
                mma16816(o[2 * dp + 1], pl[kp], &vh[dp][2]);
            }
        }
    }

    float il0 = 1.0f / l0, il1 = 1.0f / l1;
    int r0 = q0 + wid * 16 + (lane >> 2);
    int cbase = h * 64 + (lane & 3) * 2;
    #pragma unroll
    for (int nt = 0; nt < 8; nt++) {
        int c = cbase + nt * 8;
        uint32_t hi, lo;
        size_t i0 = ((size_t)b * S_ + r0) * D_ + c;
        split2(o[nt][0] * il0, o[nt][1] * il0, hi, lo);
        *(uint32_t*)(cth + i0) = hi;
        *(uint32_t*)(ctl + i0) = lo;
        size_t i1 = i0 + 8 * D_;
        split2(o[nt][2] * il1, o[nt][3] * il1, hi, lo);
        *(uint32_t*)(cth + i1) = hi;
        *(uint32_t*)(ctl + i1) = lo;
    }
}

// ---------------- launch ----------------
extern "C" void kernel_launch(void* const* d_in, const int* in_sizes, int n_in,
                              void* d_out, int out_size)
{
    const float* x    = (const float*)d_in[0];
    const float* Wqkv = (const float*)d_in[1];
    const float* Wout = (const float*)d_in[2];
    const unsigned char* mask = (const unsigned char*)d_in[3];
    float* out = (float*)d_out;

    __nv_bfloat16 *xh, *xl, *wqh, *wql, *woh, *wol, *qvh, *qvl, *cth, *ctl;
    cudaGetSymbolAddress((void**)&xh,  g_xh);
    cudaGetSymbolAddress((void**)&xl,  g_xl);
    cudaGetSymbolAddress((void**)&wqh, g_wqkvh);
    cudaGetSymbolAddress((void**)&wql, g_wqkvl);
    cudaGetSymbolAddress((void**)&woh, g_wouth);
    cudaGetSymbolAddress((void**)&wol, g_woutl);
    cudaGetSymbolAddress((void**)&qvh, g_qkvh);
    cudaGetSymbolAddress((void**)&qvl, g_qkvl);
    cudaGetSymbolAddress((void**)&cth, g_ctxh);
    cudaGetSymbolAddress((void**)&ctl, g_ctxl);

    const int gemm_smem = 2 * GSTAGE_B;
    const int flash_smem = FSMEM_TOTAL;
    static int attrs_set = 0;
    if (!attrs_set) {
        cudaFuncSetAttribute(gemm_mma, cudaFuncAttributeMaxDynamicSharedMemorySize, gemm_smem);
        cudaFuncSetAttribute(flash_mma, cudaFuncAttributeMaxDynamicSharedMemorySize, flash_smem);
        attrs_set = 1;
    }

    {
        int n4x = (B_ * S_ * D_) / 4;
        split_bf16<<<(n4x + 255) / 256, 256>>>(x, xh, xl, n4x);
        int n4w = (3 * D_ * D_) / 4;
        split_bf16<<<(n4w + 255) / 256, 256>>>(Wqkv, wqh, wql, n4w);
        int n4o = (D_ * D_) / 4;
        split_bf16<<<(n4o + 255) / 256, 256>>>(Wout, woh, wol, n4o);
    }

    {
        dim3 grid((3 * D_) / 128, (B_ * S_) / 128);
        gemm_mma<<<grid, 256, gemm_smem>>>(xh, xl, wqh, wql, nullptr, qvh, qvl, 3 * D_, D_, 1);
    }
    {
        dim3 grid(S_ / 64, B_ * H_);
        flash_mma<<<grid, 128, flash_smem>>>(qvh, qvl, mask, cth, ctl);
    }
    {
        dim3 grid(D_ / 128, (B_ * S_) / 128);
        gemm_mma<<<grid, 256, gemm_smem>>>(cth, ctl, woh, wol, out, nullptr, nullptr, D_, D_, 0);
    }
}

// round 5
// speedup vs baseline: 3.4939x; 1.0121x over previous
#include <cuda_runtime.h>
#include <cuda_bf16.h>
#include <math.h>
#include <stdint.h>

#define B_  2
#define S_  2048
#define D_  1024
#define H_  16
#define DK_ 64
#define SCALE_ 0.125f
#define LOG2E_ 1.44269504f
#define TNEG_ (-86562.0f)   // -60000 * log2(e)

// ---------------- scratch ----------------
__device__ __nv_bfloat16 g_xh[B_ * S_ * D_];
__device__ __nv_bfloat16 g_xl[B_ * S_ * D_];
__device__ __nv_bfloat16 g_wqkvh[3 * D_ * D_];
__device__ __nv_bfloat16 g_wqkvl[3 * D_ * D_];
__device__ __nv_bfloat16 g_wouth[D_ * D_];
__device__ __nv_bfloat16 g_woutl[D_ * D_];
__device__ __nv_bfloat16 g_qkvh[B_ * S_ * 3 * D_];
__device__ __nv_bfloat16 g_qkvl[B_ * S_ * 3 * D_];
__device__ __nv_bfloat16 g_ctxh[B_ * S_ * D_];
__device__ __nv_bfloat16 g_ctxl[B_ * S_ * D_];

// ================= helpers =================
__device__ __forceinline__ uint32_t smem_u32(const void* p) {
    uint32_t a;
    asm("{ .reg .u64 t; cvta.to.shared.u64 t, %1; cvt.u32.u64 %0, t; }" : "=r"(a) : "l"(p));
    return a;
}
#define CP16(dst, src) asm volatile("cp.async.cg.shared.global [%0], [%1], 16;" :: "r"(dst), "l"(src) : "memory")
#define CP_COMMIT()    asm volatile("cp.async.commit_group;" ::: "memory")
#define CP_WAIT0()     asm volatile("cp.async.wait_group 0;" ::: "memory")

__device__ __forceinline__ void ldsm4(uint32_t* r, uint32_t addr) {
    asm volatile("ldmatrix.sync.aligned.m8n8.x4.shared.b16 {%0,%1,%2,%3}, [%4];"
        : "=r"(r[0]), "=r"(r[1]), "=r"(r[2]), "=r"(r[3]) : "r"(addr));
}
__device__ __forceinline__ void ldsm4t(uint32_t* r, uint32_t addr) {
    asm volatile("ldmatrix.sync.aligned.m8n8.x4.trans.shared.b16 {%0,%1,%2,%3}, [%4];"
        : "=r"(r[0]), "=r"(r[1]), "=r"(r[2]), "=r"(r[3]) : "r"(addr));
}
__device__ __forceinline__ void mma16816(float* d, const uint32_t* a, const uint32_t* b) {
    asm volatile("mma.sync.aligned.m16n8k16.row.col.f32.bf16.bf16.f32 "
        "{%0,%1,%2,%3}, {%4,%5,%6,%7}, {%8,%9}, {%0,%1,%2,%3};"
        : "+f"(d[0]), "+f"(d[1]), "+f"(d[2]), "+f"(d[3])
        : "r"(a[0]), "r"(a[1]), "r"(a[2]), "r"(a[3]), "r"(b[0]), "r"(b[1]));
}
__device__ __forceinline__ float ex2(float x) {
    float y; asm("ex2.approx.ftz.f32 %0, %1;" : "=f"(y) : "f"(x)); return y;
}
__device__ __forceinline__ void split2(float a, float b, uint32_t& hi, uint32_t& lo) {
    __nv_bfloat16 ha = __float2bfloat16(a), hb = __float2bfloat16(b);
    hi = (uint32_t)__bfloat16_as_ushort(ha) | ((uint32_t)__bfloat16_as_ushort(hb) << 16);
    __nv_bfloat16 la = __float2bfloat16(a - __bfloat162float(ha));
    __nv_bfloat16 lb = __float2bfloat16(b - __bfloat162float(hb));
    lo = (uint32_t)__bfloat16_as_ushort(la) | ((uint32_t)__bfloat16_as_ushort(lb) << 16);
}

// ================= split fp32 -> bf16 hi/lo =================
__global__ void split_bf16(const float* __restrict__ in, __nv_bfloat16* __restrict__ hi,
                           __nv_bfloat16* __restrict__ lo, int n4) {
    int i = blockIdx.x * blockDim.x + threadIdx.x;
    if (i >= n4) return;
    float4 v = ((const float4*)in)[i];
    uint32_t h0, l0, h1, l1;
    split2(v.x, v.y, h0, l0);
    split2(v.z, v.w, h1, l1);
    ((uint2*)hi)[i] = make_uint2(h0, h1);
    ((uint2*)lo)[i] = make_uint2(l0, l1);
}

// ================= warp-MMA split-bf16 GEMM (BK=32, 2 CTAs/SM) =================
// smem row stride 80B for 64B of data -> ldsm bank-conflict-free (5r+c mod 8 is a permutation)
#define GSTRIDE_B 80
#define GTILE_B (128 * GSTRIDE_B)       // 10240
#define GSTAGE_B (4 * GTILE_B)          // 40960  (Ah, Al, Bh, Bl)

__global__ __launch_bounds__(256, 2)
void gemm_mma(const __nv_bfloat16* __restrict__ Ah, const __nv_bfloat16* __restrict__ Al,
              const __nv_bfloat16* __restrict__ Bh, const __nv_bfloat16* __restrict__ Bl,
              float* __restrict__ Cf, __nv_bfloat16* __restrict__ Ch, __nv_bfloat16* __restrict__ Cl,
              int N, int K, int split_out)
{
    extern __shared__ char sm[];
    const int tid = threadIdx.x, wid = tid >> 5, lane = tid & 31;
    const int wm = wid & 3, wn = wid >> 2;   // 4(m) x 2(n): 32 rows x 64 cols per warp
    uint32_t sbase = smem_u32(sm);

    const char* gt[4];
    gt[0] = (const char*)(Ah + (size_t)blockIdx.y * 128 * K);
    gt[1] = (const char*)(Al + (size_t)blockIdx.y * 128 * K);
    gt[2] = (const char*)(Bh + (size_t)blockIdx.x * 128 * K);
    gt[3] = (const char*)(Bl + (size_t)blockIdx.x * 128 * K);

    float acc[2][8][4] = {};

    // per stage: 4 tiles x 128 rows x 64B = 2048 16B-chunks; 8 per thread
    const int lrow = tid >> 2, lcol = tid & 3;          // 64 rows per pass, 4 chunks/row
    auto load_stage = [&](int j) {
        uint32_t sb = sbase + (j & 1) * GSTAGE_B;
        const size_t gcol = (size_t)j * 64;             // byte offset in K (32 bf16)
        #pragma unroll
        for (int t = 0; t < 4; t++) {
            const char* g = gt[t] + gcol;
            uint32_t tb = sb + t * GTILE_B;
            #pragma unroll
            for (int i = 0; i < 2; i++) {
                int row = lrow + i * 64;
                CP16(tb + row * GSTRIDE_B + lcol * 16,
                     g + (size_t)row * K * 2 + lcol * 16);
            }
        }
    };

    load_stage(0); CP_COMMIT();
    const int NK = K / 32;

    const uint32_t arow = (lane & 15), acs = (lane >> 4) * 16;
    const uint32_t brow = (lane & 7) + (lane >> 4) * 8, bcs = ((lane >> 3) & 1) * 16;

    for (int j = 0; j < NK; j++) {
        CP_WAIT0();
        __syncthreads();
        if (j + 1 < NK) { load_stage(j + 1); CP_COMMIT(); }

        uint32_t sb = sbase + (j & 1) * GSTAGE_B;
        uint32_t aH = sb + wm * 32 * GSTRIDE_B;
        uint32_t aL = aH + GTILE_B;
        uint32_t bH = sb + 2 * GTILE_B + wn * 64 * GSTRIDE_B;
        uint32_t bL = bH + GTILE_B;

        #pragma unroll
        for (int ks = 0; ks < 2; ks++) {
            uint32_t ah[2][4], al[2][4];
            #pragma unroll
            for (int mt = 0; mt < 2; mt++) {
                ldsm4(ah[mt], aH + (mt * 16 + arow) * GSTRIDE_B + ks * 32 + acs);
                ldsm4(al[mt], aL + (mt * 16 + arow) * GSTRIDE_B + ks * 32 + acs);
            }
            #pragma unroll
            for (int np = 0; np < 4; np++) {
                uint32_t bh[4], bl[4];
                ldsm4(bh, bH + (np * 16 + brow) * GSTRIDE_B + ks * 32 + bcs);
                ldsm4(bl, bL + (np * 16 + brow) * GSTRIDE_B + ks * 32 + bcs);
                #pragma unroll
                for (int mt = 0; mt < 2; mt++) {
                    mma16816(acc[mt][2 * np],     ah[mt], &bh[0]);
                    mma16816(acc[mt][2 * np + 1], ah[mt], &bh[2]);
                    mma16816(acc[mt][2 * np],     ah[mt], &bl[0]);
                    mma16816(acc[mt][2 * np + 1], ah[mt], &bl[2]);
                    mma16816(acc[mt][2 * np],     al[mt], &bh[0]);
                    mma16816(acc[mt][2 * np + 1], al[mt], &bh[2]);
                }
            }
        }
    }

    const int rb = blockIdx.y * 128 + wm * 32 + (lane >> 2);
    const int cb = blockIdx.x * 128 + wn * 64 + (lane & 3) * 2;
    #pragma unroll
    for (int mt = 0; mt < 2; mt++)
        #pragma unroll
        for (int half = 0; half < 2; half++) {
            int r = rb + mt * 16 + half * 8;
            #pragma unroll
            for (int nt = 0; nt < 8; nt++) {
                int c = cb + nt * 8;
                float v0 = acc[mt][nt][half * 2 + 0];
                float v1 = acc[mt][nt][half * 2 + 1];
                if (split_out) {
                    uint32_t hi, lo;
                    split2(v0, v1, hi, lo);
                    *(uint32_t*)(Ch + (size_t)r * N + c) = hi;
                    *(uint32_t*)(Cl + (size_t)r * N + c) = lo;
                } else {
                    *(float2*)(Cf + (size_t)r * N + c) = make_float2(v0, v1);
                }
            }
        }
}

// ================= flash attention, warp-MMA split-bf16 (unchanged) =================
#define FSTRIDE_B 144
#define FTILE_B (64 * FSTRIDE_B)        // 9216
#define FSTAGE_B (4 * FTILE_B)
#define FQ_OFF 0
#define FST_OFF (2 * FTILE_B)
#define FMS_OFF (FST_OFF + 2 * FSTAGE_B)
#define FSMEM_TOTAL (FMS_OFF + 128)

__global__ __launch_bounds__(128, 2)
void flash_mma(const __nv_bfloat16* __restrict__ qh, const __nv_bfloat16* __restrict__ ql,
               const unsigned char* __restrict__ mask,
               __nv_bfloat16* __restrict__ cth, __nv_bfloat16* __restrict__ ctl)
{
    extern __shared__ char sm[];
    const int tid = threadIdx.x, wid = tid >> 5, lane = tid & 31;
    const int bh = blockIdx.y, b = bh >> 4, h = bh & 15;
    const int q0 = blockIdx.x * 64;
    uint32_t sbase = smem_u32(sm);
    const uint32_t QH = sbase + FQ_OFF, QL = QH + FTILE_B;
    const uint32_t STG = sbase + FST_OFF;

    const size_t rs = 3 * D_;
    const char* qbh = (const char*)(qh + ((size_t)b * S_ + q0) * rs + h * 64);
    const char* qbl = (const char*)(ql + ((size_t)b * S_ + q0) * rs + h * 64);
    const char* kbh = (const char*)(qh + (size_t)b * S_ * rs + D_ + h * 64);
    const char* kbl = (const char*)(ql + (size_t)b * S_ * rs + D_ + h * 64);
    const char* vbh = (const char*)(qh + (size_t)b * S_ * rs + 2 * D_ + h * 64);
    const char* vbl = (const char*)(ql + (size_t)b * S_ * rs + 2 * D_ + h * 64);

    auto load_kv = [&](int j) {
        uint32_t sb = STG + (j & 1) * FSTAGE_B;
        size_t gk = (size_t)j * 64 * rs * 2;
        #pragma unroll
        for (int i = 0; i < 4; i++) {
            int c = tid + i * 128;
            int row = c >> 3, col = c & 7;
            size_t go = gk + (size_t)row * rs * 2 + col * 16;
            uint32_t so = row * FSTRIDE_B + col * 16;
            CP16(sb + 0 * FTILE_B + so, kbh + go);
            CP16(sb + 1 * FTILE_B + so, kbl + go);
            CP16(sb + 2 * FTILE_B + so, vbh + go);
            CP16(sb + 3 * FTILE_B + so, vbl + go);
        }
    };
    auto store_mask = [&](int j) {
        if (tid < 16) {
            uint32_t v = *(const uint32_t*)(mask + (size_t)b * S_ + j * 64 + tid * 4);
            *(uint32_t*)(sm + FMS_OFF + (j & 1) * 64 + tid * 4) = v;
        }
    };

    #pragma unroll
    for (int i = 0; i < 4; i++) {
        int c = tid + i * 128;
        int row = c >> 3, col = c & 7;
        uint32_t so = row * FSTRIDE_B + col * 16;
        CP16(QH + so, qbh + (size_t)row * rs * 2 + col * 16);
        CP16(QL + so, qbl + (size_t)row * rs * 2 + col * 16);
    }
    load_kv(0); CP_COMMIT();
    store_mask(0);

    uint32_t qfh[4][4], qfl[4][4];
    float o[8][4] = {};
    float m0 = -1e30f, m1 = -1e30f, l0 = 0.0f, l1 = 0.0f;

    const uint32_t arow = (lane & 15), acs = (lane >> 4) * 16;
    const uint32_t brow = (lane & 7) + (lane >> 4) * 8, bcs = ((lane >> 3) & 1) * 16;

    for (int kt = 0; kt < S_ / 64; kt++) {
        CP_WAIT0();
        __syncthreads();
        if (kt == 0) {
            #pragma unroll
            for (int ks = 0; ks < 4; ks++) {
                ldsm4(qfh[ks], QH + (wid * 16 + arow) * FSTRIDE_B + ks * 32 + acs);
                ldsm4(qfl[ks], QL + (wid * 16 + arow) * FSTRIDE_B + ks * 32 + acs);
            }
        }
        if (kt + 1 < S_ / 64) { load_kv(kt + 1); CP_COMMIT(); store_mask(kt + 1); }

        uint32_t sb = STG + (kt & 1) * FSTAGE_B;
        uint32_t KH = sb, KL = sb + FTILE_B, VH = sb + 2 * FTILE_B, VL = sb + 3 * FTILE_B;

        float s[8][4] = {};
        #pragma unroll
        for (int ks = 0; ks < 4; ks++) {
            uint32_t kh[4][4], kl[4][4];
            #pragma unroll
            for (int np = 0; np < 4; np++) {
                ldsm4(kh[np], KH + (np * 16 + brow) * FSTRIDE_B + ks * 32 + bcs);
                ldsm4(kl[np], KL + (np * 16 + brow) * FSTRIDE_B + ks * 32 + bcs);
            }
            #pragma unroll
            for (int np = 0; np < 4; np++) {
                mma16816(s[2 * np],     qfh[ks], &kh[np][0]);
                mma16816(s[2 * np + 1], qfh[ks], &kh[np][2]);
            }
            #pragma unroll
            for (int np = 0; np < 4; np++) {
                mma16816(s[2 * np],     qfh[ks], &kl[np][0]);
                mma16816(s[2 * np + 1], qfh[ks], &kl[np][2]);
            }
            #pragma unroll
            for (int np = 0; np < 4; np++) {
                mma16816(s[2 * np],     qfl[ks], &kh[np][0]);
                mma16816(s[2 * np + 1], qfl[ks], &kh[np][2]);
            }
        }

        const float CM = SCALE_ * LOG2E_;
        float rmax0 = -1e30f, rmax1 = -1e30f;
        #pragma unroll
        for (int nt = 0; nt < 8; nt++) {
            unsigned short mm = *(const unsigned short*)(sm + FMS_OFF + (kt & 1) * 64 + nt * 8 + (lane & 3) * 2);
            bool k0m = (mm & 0xFF) != 0, k1m = (mm >> 8) != 0;
            s[nt][0] = k0m ? TNEG_ : s[nt][0] * CM;
            s[nt][1] = k1m ? TNEG_ : s[nt][1] * CM;
            s[nt][2] = k0m ? TNEG_ : s[nt][2] * CM;
            s[nt][3] = k1m ? TNEG_ : s[nt][3] * CM;
            rmax0 = fmaxf(rmax0, fmaxf(s[nt][0], s[nt][1]));
            rmax1 = fmaxf(rmax1, fmaxf(s[nt][2], s[nt][3]));
        }
        rmax0 = fmaxf(rmax0, __shfl_xor_sync(0xffffffffu, rmax0, 1));
        rmax0 = fmaxf(rmax0, __shfl_xor_sync(0xffffffffu, rmax0, 2));
        rmax1 = fmaxf(rmax1, __shfl_xor_sync(0xffffffffu, rmax1, 1));
        rmax1 = fmaxf(rmax1, __shfl_xor_sync(0xffffffffu, rmax1, 2));
        float mn0 = fmaxf(m0, rmax0), mn1 = fmaxf(m1, rmax1);
        float cr0 = ex2(m0 - mn0), cr1 = ex2(m1 - mn1);
        m0 = mn0; m1 = mn1;
        float ps0 = 0.0f, ps1 = 0.0f;
        #pragma unroll
        for (int nt = 0; nt < 8; nt++) {
            s[nt][0] = ex2(s[nt][0] - mn0);
            s[nt][1] = ex2(s[nt][1] - mn0);
            s[nt][2] = ex2(s[nt][2] - mn1);
            s[nt][3] = ex2(s[nt][3] - mn1);
            ps0 += s[nt][0] + s[nt][1];
            ps1 += s[nt][2] + s[nt][3];
        }
        ps0 += __shfl_xor_sync(0xffffffffu, ps0, 1);
        ps0 += __shfl_xor_sync(0xffffffffu, ps0, 2);
        ps1 += __shfl_xor_sync(0xffffffffu, ps1, 1);
        ps1 += __shfl_xor_sync(0xffffffffu, ps1, 2);
        l0 = l0 * cr0 + ps0;
        l1 = l1 * cr1 + ps1;
        #pragma unroll
        for (int nt = 0; nt < 8; nt++) {
            o[nt][0] *= cr0; o[nt][1] *= cr0;
            o[nt][2] *= cr1; o[nt][3] *= cr1;
        }

        uint32_t ph[4][4], pl[4][4];
        #pragma unroll
        for (int kp = 0; kp < 4; kp++) {
            split2(s[2 * kp][0],     s[2 * kp][1],     ph[kp][0], pl[kp][0]);
            split2(s[2 * kp][2],     s[2 * kp][3],     ph[kp][1], pl[kp][1]);
            split2(s[2 * kp + 1][0], s[2 * kp + 1][1], ph[kp][2], pl[kp][2]);
            split2(s[2 * kp + 1][2], s[2 * kp + 1][3], ph[kp][3], pl[kp][3]);
        }

        #pragma unroll
        for (int kp = 0; kp < 4; kp++) {
            uint32_t vh[4][4], vl[4][4];
            uint32_t krow = kp * 16 + (lane & 15);
            uint32_t dbyte = (lane >> 4) * 16;
            #pragma unroll
            for (int dp = 0; dp < 4; dp++) {
                ldsm4t(vh[dp], VH + krow * FSTRIDE_B + dp * 32 + dbyte);
                ldsm4t(vl[dp], VL + krow * FSTRIDE_B + dp * 32 + dbyte);
            }
            #pragma unroll
            for (int dp = 0; dp < 4; dp++) {
                mma16816(o[2 * dp],     ph[kp], &vh[dp][0]);
                mma16816(o[2 * dp + 1], ph[kp], &vh[dp][2]);
            }
            #pragma unroll
            for (int dp = 0; dp < 4; dp++) {
                mma16816(o[2 * dp],     ph[kp], &vl[dp][0]);
                mma16816(o[2 * dp + 1], ph[kp], &vl[dp][2]);
            }
            #pragma unroll
            for (int dp = 0; dp < 4; dp++) {
                mma16816(o[2 * dp],     pl[kp], &vh[dp][0]);
                mma16816(o[2 * dp + 1], pl[kp], &vh[dp][2]);
            }
        }
    }

    float il0 = 1.0f / l0, il1 = 1.0f / l1;
    int r0 = q0 + wid * 16 + (lane >> 2);
    int cbase = h * 64 + (lane & 3) * 2;
    #pragma unroll
    for (int nt = 0; nt < 8; nt++) {
        int c = cbase + nt * 8;
        uint32_t hi, lo;
        size_t i0 = ((size_t)b * S_ + r0) * D_ + c;
        split2(o[nt][0] * il0, o[nt][1] * il0, hi, lo);
        *(uint32_t*)(cth + i0) = hi;
        *(uint32_t*)(ctl + i0) = lo;
        size_t i1 = i0 + 8 * D_;
        split2(o[nt][2] * il1, o[nt][3] * il1, hi, lo);
        *(uint32_t*)(cth + i1) = hi;
        *(uint32_t*)(ctl + i1) = lo;
    }
}

// ---------------- launch ----------------
extern "C" void kernel_launch(void* const* d_in, const int* in_sizes, int n_in,
                              void* d_out, int out_size)
{
    const float* x    = (const float*)d_in[0];
    const float* Wqkv = (const float*)d_in[1];
    const float* Wout = (const float*)d_in[2];
    const unsigned char* mask = (const unsigned char*)d_in[3];
    float* out = (float*)d_out;

    __nv_bfloat16 *xh, *xl, *wqh, *wql, *woh, *wol, *qvh, *qvl, *cth, *ctl;
    cudaGetSymbolAddress((void**)&xh,  g_xh);
    cudaGetSymbolAddress((void**)&xl,  g_xl);
    cudaGetSymbolAddress((void**)&wqh, g_wqkvh);
    cudaGetSymbolAddress((void**)&wql, g_wqkvl);
    cudaGetSymbolAddress((void**)&woh, g_wouth);
    cudaGetSymbolAddress((void**)&wol, g_woutl);
    cudaGetSymbolAddress((void**)&qvh, g_qkvh);
    cudaGetSymbolAddress((void**)&qvl, g_qkvl);
    cudaGetSymbolAddress((void**)&cth, g_ctxh);
    cudaGetSymbolAddress((void**)&ctl, g_ctxl);

    const int gemm_smem = 2 * GSTAGE_B;     // 81920 -> 2 CTAs/SM
    const int flash_smem = FSMEM_TOTAL;
    static int attrs_set = 0;
    if (!attrs_set) {
        cudaFuncSetAttribute(gemm_mma, cudaFuncAttributeMaxDynamicSharedMemorySize, gemm_smem);
        cudaFuncSetAttribute(flash_mma, cudaFuncAttributeMaxDynamicSharedMemorySize, flash_smem);
        attrs_set = 1;
    }

    {
        int n4x = (B_ * S_ * D_) / 4;
        split_bf16<<<(n4x + 255) / 256, 256>>>(x, xh, xl, n4x);
        int n4w = (3 * D_ * D_) / 4;
        split_bf16<<<(n4w + 255) / 256, 256>>>(Wqkv, wqh, wql, n4w);
        int n4o = (D_ * D_) / 4;
        split_bf16<<<(n4o + 255) / 256, 256>>>(Wout, woh, wol, n4o);
    }

    {
        dim3 grid((3 * D_) / 128, (B_ * S_) / 128);
        gemm_mma<<<grid, 256, gemm_smem>>>(xh, xl, wqh, wql, nullptr, qvh, qvl, 3 * D_, D_, 1);
    }
    {
        dim3 grid(S_ / 64, B_ * H_);
        flash_mma<<<grid, 128, flash_smem>>>(qvh, qvl, mask, cth, ctl);
    }
    {
        dim3 grid(D_ / 128, (B_ * S_) / 128);
        gemm_mma<<<grid, 256, gemm_smem>>>(cth, ctl, woh, wol, out, nullptr, nullptr, D_, D_, 0);
    }
}